// round 16
// baseline (speedup 1.0000x reference)
#include <cuda_runtime.h>
#include <cuda_fp16.h>
#include <cstdint>

// Problem constants (fixed by the dataset's setup_inputs)
#define HH   12
#define LL   512
#define QKVN 2304       // 3*768
#define NNZZ 2048       // B*L
#define BHH  48         // B*H

// Scratch (allocation-free rule: __device__ globals)
__device__ __half g_qkvh[(size_t)NNZZ * QKVN];   // QKV output, fp16
__device__ __half g_xh[(size_t)NNZZ * 768];      // X in fp16
__device__ __half g_wh[(size_t)QKVN * 768];      // W in fp16

// ---------------------------------------------------------------------------
// helpers
// ---------------------------------------------------------------------------
__device__ __forceinline__ uint32_t smem_u32(const void* p) {
    uint32_t a;
    asm("{ .reg .u64 t; cvta.to.shared.u64 t, %1; cvt.u32.u64 %0, t; }"
        : "=r"(a) : "l"(p));
    return a;
}
__device__ __forceinline__ void mma_f16(float* c, const uint32_t* a, const uint32_t* b) {
    asm volatile(
        "mma.sync.aligned.m16n8k16.row.col.f32.f16.f16.f32 "
        "{%0,%1,%2,%3},{%4,%5,%6,%7},{%8,%9},{%0,%1,%2,%3};"
        : "+f"(c[0]), "+f"(c[1]), "+f"(c[2]), "+f"(c[3])
        : "r"(a[0]), "r"(a[1]), "r"(a[2]), "r"(a[3]), "r"(b[0]), "r"(b[1]));
}
// fp16-accumulator MMA: D(2regs) = A*B + C(2regs)
__device__ __forceinline__ void mma_f16h(uint32_t* d, const uint32_t* a,
                                         const uint32_t* b, const uint32_t* cc) {
    asm volatile(
        "mma.sync.aligned.m16n8k16.row.col.f16.f16.f16.f16 "
        "{%0,%1},{%2,%3,%4,%5},{%6,%7},{%8,%9};"
        : "=r"(d[0]), "=r"(d[1])
        : "r"(a[0]), "r"(a[1]), "r"(a[2]), "r"(a[3]), "r"(b[0]), "r"(b[1]),
          "r"(cc[0]), "r"(cc[1]));
}
__device__ __forceinline__ void ldm_x4(uint32_t* r, uint32_t addr) {
    asm volatile("ldmatrix.sync.aligned.m8n8.x4.shared.b16 {%0,%1,%2,%3}, [%4];"
                 : "=r"(r[0]), "=r"(r[1]), "=r"(r[2]), "=r"(r[3]) : "r"(addr));
}
__device__ __forceinline__ void ldm_x4t(uint32_t* r, uint32_t addr) {
    asm volatile("ldmatrix.sync.aligned.m8n8.x4.trans.shared.b16 {%0,%1,%2,%3}, [%4];"
                 : "=r"(r[0]), "=r"(r[1]), "=r"(r[2]), "=r"(r[3]) : "r"(addr));
}
__device__ __forceinline__ void cp16(uint32_t dst, const void* src) {
    asm volatile("cp.async.cg.shared.global [%0], [%1], 16;" :: "r"(dst), "l"(src));
}
__device__ __forceinline__ void cp_commit() { asm volatile("cp.async.commit_group;"); }
__device__ __forceinline__ void cp_wait1()  { asm volatile("cp.async.wait_group 1;"); }
__device__ __forceinline__ void cp_wait0()  { asm volatile("cp.async.wait_group 0;"); }

// ---------------------------------------------------------------------------
// Kernel 0: fp32 -> fp16 convert (R15 version, near stream roofline)
// ---------------------------------------------------------------------------
__global__ void __launch_bounds__(256) cvt_f2h(const float* __restrict__ X,
                                               const float* __restrict__ W) {
    const int n4x = NNZZ * 768 / 4;                 // 393216
    const int base = blockIdx.x * 1024 + threadIdx.x;

    float4 v[4];
    const float* src[4];
    __half* dst[4];
    int j[4];
#pragma unroll
    for (int u = 0; u < 4; u++) {
        const int i = base + u * 256;
        const bool isX = i < n4x;
        src[u] = isX ? X : W;
        dst[u] = isX ? g_xh : g_wh;
        j[u]   = isX ? i : i - n4x;
    }
#pragma unroll
    for (int u = 0; u < 4; u++)
        v[u] = ((const float4*)src[u])[j[u]];
#pragma unroll
    for (int u = 0; u < 4; u++) {
        __half2 h0 = __floats2half2_rn(v[u].x, v[u].y);
        __half2 h1 = __floats2half2_rn(v[u].z, v[u].w);
        uint2 uu;
        uu.x = *reinterpret_cast<uint32_t*>(&h0);
        uu.y = *reinterpret_cast<uint32_t*>(&h1);
        *reinterpret_cast<uint2*>(dst[u] + 4 * (size_t)j[u]) = uu;
    }
}

// ---------------------------------------------------------------------------
// Kernel A: QKV = X @ W^T + b. NEW: fp16-accumulator MMAs within each ktile
// (K=32, 2 chained f16-D MMAs), promoted to fp32 once per ktile. If the HMMA
// fp16-acc path runs 2x the fp32-acc rate, the tensor floor halves.
// ---------------------------------------------------------------------------
__global__ void __launch_bounds__(256, 2) qkv_h(const float* __restrict__ Wb) {
    __shared__ __align__(16) __half sA[3][128 * 40];
    __shared__ __align__(16) __half sB[3][128 * 40];
    __shared__ float sWb[128];

    const int t    = threadIdx.x;
    const int w    = t >> 5, lane = t & 31;
    const int g    = lane >> 2, t3 = lane & 3;
    const int wm   = (w >> 2) * 64;
    const int wn   = (w & 3) * 32;
    const int m0   = blockIdx.y * 128;
    const int n0   = blockIdx.x * 128;

    if (t < 128) sWb[t] = Wb[n0 + t];

    float c[4][4][4];
#pragma unroll
    for (int mf = 0; mf < 4; mf++)
#pragma unroll
        for (int nf = 0; nf < 4; nf++)
#pragma unroll
            for (int r = 0; r < 4; r++) c[mf][nf][r] = 0.f;

    const uint32_t aB = smem_u32(&sA[0][0]);
    const uint32_t bB = smem_u32(&sB[0][0]);

    const int arow = lane & 15;
    const int acol = (lane >> 4) * 16;
    const int brow = (lane & 7) + ((lane >> 4) & 1) * 8;
    const int bcol = ((lane >> 3) & 1) * 16;

    auto load_stage = [&](int st, int kt) {
        const int k0 = kt * 32;
#pragma unroll
        for (int i = 0; i < 2; i++) {
            const int idx = t + 256 * i;
            const int row = idx >> 2, seg = idx & 3;
            cp16(aB + (uint32_t)(st * 10240 + row * 80 + seg * 16),
                 g_xh + (size_t)(m0 + row) * 768 + k0 + seg * 8);
            cp16(bB + (uint32_t)(st * 10240 + row * 80 + seg * 16),
                 g_wh + (size_t)(n0 + row) * 768 + k0 + seg * 8);
        }
        cp_commit();
    };

    load_stage(0, 0);
    load_stage(1, 1);
    for (int kt = 0; kt < 24; kt++) {
        const int st = kt % 3;
        if (kt < 23) cp_wait1(); else cp_wait0();
        __syncthreads();
        if (kt + 2 < 24) load_stage((kt + 2) % 3, kt + 2);

        // fp16 accumulators for this ktile
        uint32_t dh[4][4][2];
#pragma unroll
        for (int ks = 0; ks < 2; ks++) {
            uint32_t a[4][4], bk[2][4];
#pragma unroll
            for (int mf = 0; mf < 4; mf++)
                ldm_x4(a[mf], aB + (uint32_t)(st * 10240 +
                       (wm + mf * 16 + arow) * 80 + acol + ks * 32));
#pragma unroll
            for (int nf2 = 0; nf2 < 2; nf2++)
                ldm_x4(bk[nf2], bB + (uint32_t)(st * 10240 +
                       (wn + nf2 * 16 + brow) * 80 + bcol + ks * 32));
#pragma unroll
            for (int mf = 0; mf < 4; mf++)
#pragma unroll
                for (int nf = 0; nf < 4; nf++) {
                    uint32_t bb[2] = { bk[nf >> 1][(nf & 1) * 2],
                                       bk[nf >> 1][(nf & 1) * 2 + 1] };
                    if (ks == 0) {
                        const uint32_t z[2] = {0u, 0u};
                        mma_f16h(dh[mf][nf], a[mf], bb, z);
                    } else {
                        mma_f16h(dh[mf][nf], a[mf], bb, dh[mf][nf]);
                    }
                }
        }
        // promote ktile partial sums to fp32
#pragma unroll
        for (int mf = 0; mf < 4; mf++)
#pragma unroll
            for (int nf = 0; nf < 4; nf++) {
                float2 f0 = __half22float2(*reinterpret_cast<__half2*>(&dh[mf][nf][0]));
                float2 f1 = __half22float2(*reinterpret_cast<__half2*>(&dh[mf][nf][1]));
                c[mf][nf][0] += f0.x;
                c[mf][nf][1] += f0.y;
                c[mf][nf][2] += f1.x;
                c[mf][nf][3] += f1.y;
            }
    }

#pragma unroll
    for (int mf = 0; mf < 4; mf++) {
        const int r0 = m0 + wm + mf * 16 + g;
#pragma unroll
        for (int nf = 0; nf < 4; nf++) {
            const int col = n0 + wn + nf * 8 + 2 * t3;
            const float b0 = sWb[col - n0], b1 = sWb[col - n0 + 1];
            __half2 h0 = __floats2half2_rn(c[mf][nf][0] + b0, c[mf][nf][1] + b1);
            __half2 h1 = __floats2half2_rn(c[mf][nf][2] + b0, c[mf][nf][3] + b1);
            *(__half2*)&g_qkvh[(size_t)r0 * QKVN + col]       = h0;
            *(__half2*)&g_qkvh[(size_t)(r0 + 8) * QKVN + col] = h1;
        }
    }
}

// ---------------------------------------------------------------------------
// Kernel B: fused attention (R15 best: P-regs + bias-regs + 3-stage K/V ring
// with depth-2 waits). Unchanged.
// ---------------------------------------------------------------------------
__global__ void __launch_bounds__(128, 4) attn_h(const float* __restrict__ bias,
                                                 float* __restrict__ out) {
    __shared__ __align__(16) __half Qs[64][72];
    __shared__ __align__(16) __half Ks[3][32][72];
    __shared__ __align__(16) __half Vs[3][32][72];

    const int t  = threadIdx.x;
    const int w  = t >> 5, lane = t & 31;
    const int g  = lane >> 2, t3 = lane & 3;
    const int q0 = blockIdx.x * 64;
    const int bh = blockIdx.y;
    const int b  = bh / HH, h = bh % HH;

    const uint32_t Qb = smem_u32(&Qs[0][0]);
    const uint32_t Kb = smem_u32(&Ks[0][0][0]);
    const uint32_t Vb = smem_u32(&Vs[0][0][0]);

    const int arow = lane & 15;
    const int acol = (lane >> 4) * 16;
    const int brow = (lane & 7) + ((lane >> 4) & 1) * 8;
    const int bcol = ((lane >> 3) & 1) * 16;
    const int vrow = (lane & 7) + ((lane >> 3) & 1) * 8;
    const int vcol = (lane >> 4) * 16;

    const int ql = w * 16 + g;
    const float* bp0 = bias + ((size_t)bh * 1024 + q0 + ql) * 1024 + 2 * t3;
    const float* bp1 = bp0 + (size_t)8 * 1024;

    auto prefetch = [&](int kc) {
        const int buf = kc % 3;
        const int k0  = kc * 32;
#pragma unroll
        for (int i = 0; i < 2; i++) {            // K + V
            const int idx = t + 128 * i;
            const int row = idx >> 3, seg = idx & 7;
            const size_t base = (size_t)(b * LL + k0 + row) * QKVN + h * 64 + seg * 8;
            cp16(Kb + (uint32_t)(buf * 4608 + row * 144 + seg * 16), g_qkvh + base + 768);
            cp16(Vb + (uint32_t)(buf * 4608 + row * 144 + seg * 16), g_qkvh + base + 1536);
        }
        cp_commit();
    };

    // Q tile folded into prefetch(0)'s commit group
#pragma unroll
    for (int i = 0; i < 4; i++) {
        const int idx = t + 128 * i;
        const int row = idx >> 3, seg = idx & 7;
        cp16(Qb + (uint32_t)(row * 144 + seg * 16),
             g_qkvh + (size_t)(b * LL + q0 + row) * QKVN + h * 64 + seg * 8);
    }
    prefetch(0);
    prefetch(1);

    // bias registers for chunk 0
    float2 bv0[4], bv1[4];
#pragma unroll
    for (int nf = 0; nf < 4; nf++) {
        bv0[nf] = *(const float2*)(bp0 + nf * 8);
        bv1[nf] = *(const float2*)(bp1 + nf * 8);
    }

    float o[8][4];
#pragma unroll
    for (int nf = 0; nf < 8; nf++)
#pragma unroll
        for (int r = 0; r < 4; r++) o[nf][r] = 0.f;
    float psum0 = 0.f, psum1 = 0.f;

    for (int kc = 0; kc < 16; kc++) {
        const int buf = kc % 3;
        if (kc < 15) cp_wait1(); else cp_wait0();
        __syncthreads();                 // chunk kc visible; buf reads done
        if (kc + 2 < 16) prefetch(kc + 2);

        // S = Q K^T   (warp: 16 q x 32 kv)
        float s[4][4];
#pragma unroll
        for (int nf = 0; nf < 4; nf++)
#pragma unroll
            for (int r = 0; r < 4; r++) s[nf][r] = 0.f;
#pragma unroll
        for (int ks = 0; ks < 4; ks++) {
            uint32_t a[4];
            ldm_x4(a, Qb + (uint32_t)((w * 16 + arow) * 144 + acol + ks * 32));
#pragma unroll
            for (int nf2 = 0; nf2 < 2; nf2++) {
                uint32_t bk[4];
                ldm_x4(bk, Kb + (uint32_t)(buf * 4608 +
                       (nf2 * 16 + brow) * 144 + bcol + ks * 32));
                mma_f16(s[nf2 * 2],     a, &bk[0]);
                mma_f16(s[nf2 * 2 + 1], a, &bk[2]);
            }
        }

        // exp (bias from registers) -> pack P into register A-fragments
        uint32_t pa[2][4];
#pragma unroll
        for (int nf = 0; nf < 4; nf++) {
            const float e0 = __expf(s[nf][0] * 0.125f + bv0[nf].x);
            const float e1 = __expf(s[nf][1] * 0.125f + bv0[nf].y);
            const float e2 = __expf(s[nf][2] * 0.125f + bv1[nf].x);
            const float e3 = __expf(s[nf][3] * 0.125f + bv1[nf].y);
            psum0 += e0 + e1;
            psum1 += e2 + e3;
            __half2 p01 = __floats2half2_rn(e0, e1);
            __half2 p23 = __floats2half2_rn(e2, e3);
            const int ks = nf >> 1, hi = (nf & 1) * 2;
            pa[ks][hi]     = *reinterpret_cast<uint32_t*>(&p01);
            pa[ks][hi + 1] = *reinterpret_cast<uint32_t*>(&p23);
        }

        // O += P V   (P from registers, V via ldmatrix.trans)
#pragma unroll
        for (int ks = 0; ks < 2; ks++) {
#pragma unroll
            for (int nf2 = 0; nf2 < 4; nf2++) {
                uint32_t bv[4];
                ldm_x4t(bv, Vb + (uint32_t)(buf * 4608 +
                        (ks * 16 + vrow) * 144 + vcol + nf2 * 32));
                mma_f16(o[nf2 * 2],     pa[ks], &bv[0]);
                mma_f16(o[nf2 * 2 + 1], pa[ks], &bv[2]);
            }
        }

        // bias for chunk kc+1: LDG issued a full phase ahead of use
        if (kc + 1 < 16) {
            const int kn = (kc + 1) * 32;
#pragma unroll
            for (int nf = 0; nf < 4; nf++) {
                bv0[nf] = *(const float2*)(bp0 + kn + nf * 8);
                bv1[nf] = *(const float2*)(bp1 + kn + nf * 8);
            }
        }
    }

    // rowsum: quad reduction gives the full row sums directly
    psum0 += __shfl_xor_sync(0xffffffffu, psum0, 1);
    psum0 += __shfl_xor_sync(0xffffffffu, psum0, 2);
    psum1 += __shfl_xor_sync(0xffffffffu, psum1, 1);
    psum1 += __shfl_xor_sync(0xffffffffu, psum1, 2);
    const float inv0 = 1.f / psum0;
    const float inv1 = 1.f / psum1;

    // epilogue: out[q][d] = O(q,d) / rowsum[q]
    const size_t row0 = (size_t)(b * LL + q0 + ql) * 768 + h * 64;
#pragma unroll
    for (int nf = 0; nf < 8; nf++) {
        const int col = nf * 8 + 2 * t3;
        *(float2*)&out[row0 + col] =
            make_float2(o[nf][0] * inv0, o[nf][1] * inv0);
        *(float2*)&out[row0 + (size_t)8 * 768 + col] =
            make_float2(o[nf][2] * inv1, o[nf][3] * inv1);
    }
}

// ---------------------------------------------------------------------------
extern "C" void kernel_launch(void* const* d_in, const int* in_sizes, int n_in,
                              void* d_out, int out_size) {
    const float* X    = (const float*)d_in[0];   // hidden_states [2048,768]
    const float* W    = (const float*)d_in[1];   // Wqkv_w [2304,768]
    const float* Wb   = (const float*)d_in[2];   // Wqkv_b [2304]
    const float* bias = (const float*)d_in[3];   // bias [4,12,1024,1024]
    float* out = (float*)d_out;                  // [2048,768] fp32

    cvt_f2h<<<816, 256>>>(X, W);
    qkv_h<<<dim3(18, 16), 256>>>(Wb);
    attn_h<<<dim3(8, BHH), 128>>>(bias, out);
}

// round 17
// speedup vs baseline: 1.0717x; 1.0717x over previous
#include <cuda_runtime.h>
#include <cuda_fp16.h>
#include <cstdint>

// Problem constants (fixed by the dataset's setup_inputs)
#define HH   12
#define LL   512
#define QKVN 2304       // 3*768
#define NNZZ 2048       // B*L
#define BHH  48         // B*H

// Scratch (allocation-free rule: __device__ globals)
__device__ __half g_qkvh[(size_t)NNZZ * QKVN];   // QKV output, fp16
__device__ __half g_xh[(size_t)NNZZ * 768];      // X in fp16
__device__ __half g_wh[(size_t)QKVN * 768];      // W in fp16

// ---------------------------------------------------------------------------
// helpers
// ---------------------------------------------------------------------------
__device__ __forceinline__ uint32_t smem_u32(const void* p) {
    uint32_t a;
    asm("{ .reg .u64 t; cvta.to.shared.u64 t, %1; cvt.u32.u64 %0, t; }"
        : "=r"(a) : "l"(p));
    return a;
}
__device__ __forceinline__ void mma_f16(float* c, const uint32_t* a, const uint32_t* b) {
    asm volatile(
        "mma.sync.aligned.m16n8k16.row.col.f32.f16.f16.f32 "
        "{%0,%1,%2,%3},{%4,%5,%6,%7},{%8,%9},{%0,%1,%2,%3};"
        : "+f"(c[0]), "+f"(c[1]), "+f"(c[2]), "+f"(c[3])
        : "r"(a[0]), "r"(a[1]), "r"(a[2]), "r"(a[3]), "r"(b[0]), "r"(b[1]));
}
__device__ __forceinline__ void ldm_x4(uint32_t* r, uint32_t addr) {
    asm volatile("ldmatrix.sync.aligned.m8n8.x4.shared.b16 {%0,%1,%2,%3}, [%4];"
                 : "=r"(r[0]), "=r"(r[1]), "=r"(r[2]), "=r"(r[3]) : "r"(addr));
}
__device__ __forceinline__ void ldm_x4t(uint32_t* r, uint32_t addr) {
    asm volatile("ldmatrix.sync.aligned.m8n8.x4.trans.shared.b16 {%0,%1,%2,%3}, [%4];"
                 : "=r"(r[0]), "=r"(r[1]), "=r"(r[2]), "=r"(r[3]) : "r"(addr));
}
__device__ __forceinline__ void cp16(uint32_t dst, const void* src) {
    asm volatile("cp.async.cg.shared.global [%0], [%1], 16;" :: "r"(dst), "l"(src));
}
__device__ __forceinline__ void cp_commit() { asm volatile("cp.async.commit_group;"); }
__device__ __forceinline__ void cp_wait1()  { asm volatile("cp.async.wait_group 1;"); }
__device__ __forceinline__ void cp_wait0()  { asm volatile("cp.async.wait_group 0;"); }

// ---------------------------------------------------------------------------
// Kernel 0: fp32 -> fp16 convert (R15 version)
// ---------------------------------------------------------------------------
__global__ void __launch_bounds__(256) cvt_f2h(const float* __restrict__ X,
                                               const float* __restrict__ W) {
    const int n4x = NNZZ * 768 / 4;                 // 393216
    const int base = blockIdx.x * 1024 + threadIdx.x;

    float4 v[4];
    const float* src[4];
    __half* dst[4];
    int j[4];
#pragma unroll
    for (int u = 0; u < 4; u++) {
        const int i = base + u * 256;
        const bool isX = i < n4x;
        src[u] = isX ? X : W;
        dst[u] = isX ? g_xh : g_wh;
        j[u]   = isX ? i : i - n4x;
    }
#pragma unroll
    for (int u = 0; u < 4; u++)
        v[u] = ((const float4*)src[u])[j[u]];
#pragma unroll
    for (int u = 0; u < 4; u++) {
        __half2 h0 = __floats2half2_rn(v[u].x, v[u].y);
        __half2 h1 = __floats2half2_rn(v[u].z, v[u].w);
        uint2 uu;
        uu.x = *reinterpret_cast<uint32_t*>(&h0);
        uu.y = *reinterpret_cast<uint32_t*>(&h1);
        *reinterpret_cast<uint2*>(dst[u] + 4 * (size_t)j[u]) = uu;
    }
}

// ---------------------------------------------------------------------------
// Kernel A: QKV = X @ W^T + b (fp16 mma m16n8k16, fp32 acc, 3-stage cp.async).
// REVERTED to R15 — confirmed at the mma.sync tensor floor.
// ---------------------------------------------------------------------------
__global__ void __launch_bounds__(256, 2) qkv_h(const float* __restrict__ Wb) {
    __shared__ __align__(16) __half sA[3][128 * 40];
    __shared__ __align__(16) __half sB[3][128 * 40];
    __shared__ float sWb[128];

    const int t    = threadIdx.x;
    const int w    = t >> 5, lane = t & 31;
    const int g    = lane >> 2, t3 = lane & 3;
    const int wm   = (w >> 2) * 64;
    const int wn   = (w & 3) * 32;
    const int m0   = blockIdx.y * 128;
    const int n0   = blockIdx.x * 128;

    if (t < 128) sWb[t] = Wb[n0 + t];

    float c[4][4][4];
#pragma unroll
    for (int mf = 0; mf < 4; mf++)
#pragma unroll
        for (int nf = 0; nf < 4; nf++)
#pragma unroll
            for (int r = 0; r < 4; r++) c[mf][nf][r] = 0.f;

    const uint32_t aB = smem_u32(&sA[0][0]);
    const uint32_t bB = smem_u32(&sB[0][0]);

    const int arow = lane & 15;
    const int acol = (lane >> 4) * 16;
    const int brow = (lane & 7) + ((lane >> 4) & 1) * 8;
    const int bcol = ((lane >> 3) & 1) * 16;

    auto load_stage = [&](int st, int kt) {
        const int k0 = kt * 32;
#pragma unroll
        for (int i = 0; i < 2; i++) {
            const int idx = t + 256 * i;
            const int row = idx >> 2, seg = idx & 3;
            cp16(aB + (uint32_t)(st * 10240 + row * 80 + seg * 16),
                 g_xh + (size_t)(m0 + row) * 768 + k0 + seg * 8);
            cp16(bB + (uint32_t)(st * 10240 + row * 80 + seg * 16),
                 g_wh + (size_t)(n0 + row) * 768 + k0 + seg * 8);
        }
        cp_commit();
    };

    load_stage(0, 0);
    load_stage(1, 1);
    for (int kt = 0; kt < 24; kt++) {
        const int st = kt % 3;
        if (kt < 23) cp_wait1(); else cp_wait0();
        __syncthreads();
        if (kt + 2 < 24) load_stage((kt + 2) % 3, kt + 2);

#pragma unroll
        for (int ks = 0; ks < 2; ks++) {
            uint32_t a[4][4], bk[2][4];
#pragma unroll
            for (int mf = 0; mf < 4; mf++)
                ldm_x4(a[mf], aB + (uint32_t)(st * 10240 +
                       (wm + mf * 16 + arow) * 80 + acol + ks * 32));
#pragma unroll
            for (int nf2 = 0; nf2 < 2; nf2++)
                ldm_x4(bk[nf2], bB + (uint32_t)(st * 10240 +
                       (wn + nf2 * 16 + brow) * 80 + bcol + ks * 32));
#pragma unroll
            for (int mf = 0; mf < 4; mf++)
#pragma unroll
                for (int nf = 0; nf < 4; nf++) {
                    uint32_t bb[2] = { bk[nf >> 1][(nf & 1) * 2],
                                       bk[nf >> 1][(nf & 1) * 2 + 1] };
                    mma_f16(c[mf][nf], a[mf], bb);
                }
        }
    }

#pragma unroll
    for (int mf = 0; mf < 4; mf++) {
        const int r0 = m0 + wm + mf * 16 + g;
#pragma unroll
        for (int nf = 0; nf < 4; nf++) {
            const int col = n0 + wn + nf * 8 + 2 * t3;
            const float b0 = sWb[col - n0], b1 = sWb[col - n0 + 1];
            __half2 h0 = __floats2half2_rn(c[mf][nf][0] + b0, c[mf][nf][1] + b1);
            __half2 h1 = __floats2half2_rn(c[mf][nf][2] + b0, c[mf][nf][3] + b1);
            *(__half2*)&g_qkvh[(size_t)r0 * QKVN + col]       = h0;
            *(__half2*)&g_qkvh[(size_t)(r0 + 8) * QKVN + col] = h1;
        }
    }
}

// ---------------------------------------------------------------------------
// Kernel B: fused attention = R15 + Q FRAGMENTS IN REGISTERS.
// Q ldmatrix addresses depend only on ks -> load the 4 A-fragments once
// (after the first chunk's data barrier) and reuse across all 16 chunks,
// deleting 60 ldmatrix per warp from the S-phase critical path.
// P-regs + bias-regs + 3-stage K/V ring with depth-2 waits (all R15).
// ---------------------------------------------------------------------------
__global__ void __launch_bounds__(128, 4) attn_h(const float* __restrict__ bias,
                                                 float* __restrict__ out) {
    __shared__ __align__(16) __half Qs[64][72];
    __shared__ __align__(16) __half Ks[3][32][72];
    __shared__ __align__(16) __half Vs[3][32][72];

    const int t  = threadIdx.x;
    const int w  = t >> 5, lane = t & 31;
    const int g  = lane >> 2, t3 = lane & 3;
    const int q0 = blockIdx.x * 64;
    const int bh = blockIdx.y;
    const int b  = bh / HH, h = bh % HH;

    const uint32_t Qb = smem_u32(&Qs[0][0]);
    const uint32_t Kb = smem_u32(&Ks[0][0][0]);
    const uint32_t Vb = smem_u32(&Vs[0][0][0]);

    const int arow = lane & 15;
    const int acol = (lane >> 4) * 16;
    const int brow = (lane & 7) + ((lane >> 4) & 1) * 8;
    const int bcol = ((lane >> 3) & 1) * 16;
    const int vrow = (lane & 7) + ((lane >> 3) & 1) * 8;
    const int vcol = (lane >> 4) * 16;

    const int ql = w * 16 + g;
    const float* bp0 = bias + ((size_t)bh * 1024 + q0 + ql) * 1024 + 2 * t3;
    const float* bp1 = bp0 + (size_t)8 * 1024;

    auto prefetch = [&](int kc) {
        const int buf = kc % 3;
        const int k0  = kc * 32;
#pragma unroll
        for (int i = 0; i < 2; i++) {            // K + V
            const int idx = t + 128 * i;
            const int row = idx >> 3, seg = idx & 7;
            const size_t base = (size_t)(b * LL + k0 + row) * QKVN + h * 64 + seg * 8;
            cp16(Kb + (uint32_t)(buf * 4608 + row * 144 + seg * 16), g_qkvh + base + 768);
            cp16(Vb + (uint32_t)(buf * 4608 + row * 144 + seg * 16), g_qkvh + base + 1536);
        }
        cp_commit();
    };

    // Q tile folded into prefetch(0)'s commit group
#pragma unroll
    for (int i = 0; i < 4; i++) {
        const int idx = t + 128 * i;
        const int row = idx >> 3, seg = idx & 7;
        cp16(Qb + (uint32_t)(row * 144 + seg * 16),
             g_qkvh + (size_t)(b * LL + q0 + row) * QKVN + h * 64 + seg * 8);
    }
    prefetch(0);
    prefetch(1);

    // bias registers for chunk 0
    float2 bv0[4], bv1[4];
#pragma unroll
    for (int nf = 0; nf < 4; nf++) {
        bv0[nf] = *(const float2*)(bp0 + nf * 8);
        bv1[nf] = *(const float2*)(bp1 + nf * 8);
    }

    float o[8][4];
#pragma unroll
    for (int nf = 0; nf < 8; nf++)
#pragma unroll
        for (int r = 0; r < 4; r++) o[nf][r] = 0.f;
    float psum0 = 0.f, psum1 = 0.f;

    uint32_t qa[4][4];   // Q A-fragments, loaded once after chunk-0 barrier

    for (int kc = 0; kc < 16; kc++) {
        const int buf = kc % 3;
        if (kc < 15) cp_wait1(); else cp_wait0();
        __syncthreads();                 // chunk kc visible; buf reads done
        if (kc + 2 < 16) prefetch(kc + 2);

        if (kc == 0) {                   // Q fragments: once for all chunks
#pragma unroll
            for (int ks = 0; ks < 4; ks++)
                ldm_x4(qa[ks], Qb + (uint32_t)((w * 16 + arow) * 144 + acol + ks * 32));
        }

        // S = Q K^T   (warp: 16 q x 32 kv), Q from registers
        float s[4][4];
#pragma unroll
        for (int nf = 0; nf < 4; nf++)
#pragma unroll
            for (int r = 0; r < 4; r++) s[nf][r] = 0.f;
#pragma unroll
        for (int ks = 0; ks < 4; ks++) {
#pragma unroll
            for (int nf2 = 0; nf2 < 2; nf2++) {
                uint32_t bk[4];
                ldm_x4(bk, Kb + (uint32_t)(buf * 4608 +
                       (nf2 * 16 + brow) * 144 + bcol + ks * 32));
                mma_f16(s[nf2 * 2],     qa[ks], &bk[0]);
                mma_f16(s[nf2 * 2 + 1], qa[ks], &bk[2]);
            }
        }

        // exp (bias from registers) -> pack P into register A-fragments
        uint32_t pa[2][4];
#pragma unroll
        for (int nf = 0; nf < 4; nf++) {
            const float e0 = __expf(s[nf][0] * 0.125f + bv0[nf].x);
            const float e1 = __expf(s[nf][1] * 0.125f + bv0[nf].y);
            const float e2 = __expf(s[nf][2] * 0.125f + bv1[nf].x);
            const float e3 = __expf(s[nf][3] * 0.125f + bv1[nf].y);
            psum0 += e0 + e1;
            psum1 += e2 + e3;
            __half2 p01 = __floats2half2_rn(e0, e1);
            __half2 p23 = __floats2half2_rn(e2, e3);
            const int ks = nf >> 1, hi = (nf & 1) * 2;
            pa[ks][hi]     = *reinterpret_cast<uint32_t*>(&p01);
            pa[ks][hi + 1] = *reinterpret_cast<uint32_t*>(&p23);
        }

        // O += P V   (P from registers, V via ldmatrix.trans)
#pragma unroll
        for (int ks = 0; ks < 2; ks++) {
#pragma unroll
            for (int nf2 = 0; nf2 < 4; nf2++) {
                uint32_t bv[4];
                ldm_x4t(bv, Vb + (uint32_t)(buf * 4608 +
                        (ks * 16 + vrow) * 144 + vcol + nf2 * 32));
                mma_f16(o[nf2 * 2],     pa[ks], &bv[0]);
                mma_f16(o[nf2 * 2 + 1], pa[ks], &bv[2]);
            }
        }

        // bias for chunk kc+1: LDG issued a full phase ahead of use
        if (kc + 1 < 16) {
            const int kn = (kc + 1) * 32;
#pragma unroll
            for (int nf = 0; nf < 4; nf++) {
                bv0[nf] = *(const float2*)(bp0 + kn + nf * 8);
                bv1[nf] = *(const float2*)(bp1 + kn + nf * 8);
            }
        }
    }

    // rowsum: quad reduction gives the full row sums directly
    psum0 += __shfl_xor_sync(0xffffffffu, psum0, 1);
    psum0 += __shfl_xor_sync(0xffffffffu, psum0, 2);
    psum1 += __shfl_xor_sync(0xffffffffu, psum1, 1);
    psum1 += __shfl_xor_sync(0xffffffffu, psum1, 2);
    const float inv0 = 1.f / psum0;
    const float inv1 = 1.f / psum1;

    // epilogue: out[q][d] = O(q,d) / rowsum[q]
    const size_t row0 = (size_t)(b * LL + q0 + ql) * 768 + h * 64;
#pragma unroll
    for (int nf = 0; nf < 8; nf++) {
        const int col = nf * 8 + 2 * t3;
        *(float2*)&out[row0 + col] =
            make_float2(o[nf][0] * inv0, o[nf][1] * inv0);
        *(float2*)&out[row0 + (size_t)8 * 768 + col] =
            make_float2(o[nf][2] * inv1, o[nf][3] * inv1);
    }
}

// ---------------------------------------------------------------------------
extern "C" void kernel_launch(void* const* d_in, const int* in_sizes, int n_in,
                              void* d_out, int out_size) {
    const float* X    = (const float*)d_in[0];   // hidden_states [2048,768]
    const float* W    = (const float*)d_in[1];   // Wqkv_w [2304,768]
    const float* Wb   = (const float*)d_in[2];   // Wqkv_b [2304]
    const float* bias = (const float*)d_in[3];   // bias [4,12,1024,1024]
    float* out = (float*)d_out;                  // [2048,768] fp32

    cvt_f2h<<<816, 256>>>(X, W);
    qkv_h<<<dim3(18, 16), 256>>>(Wb);
    attn_h<<<dim3(8, BHH), 128>>>(bias, out);
}